// round 4
// baseline (speedup 1.0000x reference)
#include <cuda_runtime.h>
#include <cuda_bf16.h>
#include <math.h>

// ---------------- problem constants ----------------
#define CH 192
#define HEADS 6
#define HD 32
#define MTOT 131072
#define HIDDEN 768
#define SROW 200   // padded smem row stride (elems) for full-K tiles

// ---------------- scratch ----------------
__device__ __nv_bfloat16 gb_qkv [(size_t)MTOT * 3 * CH];
__device__ __nv_bfloat16 gb_attn[(size_t)MTOT * CH];
__device__ float         g_x1   [(size_t)MTOT * CH];
__device__ __nv_bfloat16 gb_hid [(size_t)MTOT * HIDDEN];
__device__ __nv_bfloat16 gb_w[576*192 + 192*192 + 768*192 + 192*768];
__device__ float g_Sq[576], g_Tq[576];   // LN1-fold vectors for QKV
__device__ float g_S1[768], g_T1[768];   // LN2-fold vectors for MLP1

__device__ __forceinline__ int gather_row(int m) {
    int win = m >> 6, n = m & 63;
    int b   = win >> 10, rem = win & 1023;
    int wh  = rem >> 5,  ww  = rem & 31;
    int r   = n >> 3,    c   = n & 7;
    int hs  = (wh * 8 + r + 4) & 255;
    int ws_ = (ww * 8 + c + 4) & 255;
    return (b << 16) | (hs << 8) | ws_;
}

__device__ __forceinline__ unsigned smem_u32(const void* p) {
    return (unsigned)__cvta_generic_to_shared(p);
}

// ---------------- fp32 -> bf16 convert (plain weights) ----------------
__global__ void f2bf_kernel(const float* __restrict__ in, __nv_bfloat16* __restrict__ out, int n) {
    int i = blockIdx.x * 256 + threadIdx.x;
    if (i < n) out[i] = __float2bfloat16(in[i]);
}

// ---------------- weight prep with LN fold: Wb = bf16(g*W); S = sum g*W; T = sum b*W (+bias) ----------------
__global__ void wprep_kernel(const float* __restrict__ W, const float* __restrict__ g,
                             const float* __restrict__ b, const float* __restrict__ bias,
                             __nv_bfloat16* __restrict__ Wb, float* __restrict__ S,
                             float* __restrict__ T) {
    int n = blockIdx.x, lane = threadIdx.x;
    float s = 0.f, tt = 0.f;
#pragma unroll
    for (int i = 0; i < 6; i++) {
        int k = lane + 32 * i;
        float w = W[(size_t)n * 192 + k];
        float gw = g[k] * w;
        s  += gw;
        tt += b[k] * w;
        Wb[(size_t)n * 192 + k] = __float2bfloat16(gw);
    }
#pragma unroll
    for (int o = 16; o; o >>= 1) {
        s  += __shfl_xor_sync(0xffffffffu, s, o);
        tt += __shfl_xor_sync(0xffffffffu, tt, o);
    }
    if (lane == 0) { S[n] = s; T[n] = tt + (bias ? bias[n] : 0.f); }
}

// ---------------- single-shot full-K (192) HMMA GEMM, 128x128 tile ----------------
// EPI: 0 = store bf16; 1 = GELU, store bf16; 2 = scatter row, +res[gathered], fp32
// LNF: A is fp32 raw x; compute row stats; epilogue applies LN fold with S/T.
template<int EPI, bool GATHER, bool LNF>
__global__ void __launch_bounds__(256, 2) gemm_fullk(
    const void* __restrict__ Ain, const __nv_bfloat16* __restrict__ W,
    const float* __restrict__ Svec, const float* __restrict__ Tvec,
    const float* __restrict__ bias, const float* __restrict__ res,
    void* __restrict__ Cout, int N)
{
    extern __shared__ __nv_bfloat16 sm[];
    __nv_bfloat16* As = sm;                       // 128*SROW
    __nv_bfloat16* Bs = sm + 128 * SROW;          // 128*SROW
    float* sMu  = (float*)(sm + 2 * 128 * SROW);  // 128
    float* sInv = sMu + 128;                      // 128

    const int m0 = blockIdx.x * 128, n0 = blockIdx.y * 128;
    const int t = threadIdx.x, lane = t & 31, wid = t >> 5;
    const int wm = wid & 1, wn = wid >> 1;        // 2(M) x 4(N) warps, each 64x32

    // ---- B tile: 12 x 16B cp.async per thread
    {
        const int r = t >> 1, col = (t & 1) * 96;
        int bg = n0 + r; if (bg >= N) bg = 0;
        const __nv_bfloat16* src = W + (size_t)bg * 192 + col;
        unsigned dst = smem_u32(Bs + r * SROW + col);
#pragma unroll
        for (int c = 0; c < 12; c++)
            asm volatile("cp.async.cg.shared.global [%0], [%1], 16;\n"
                :: "r"(dst + c * 16), "l"(src + c * 8));
    }

    // ---- A tile
    if (LNF) {
        // fp32 load, accumulate row stats, convert to bf16 smem
        const int r = t >> 1, half = t & 1;
        const int arow = GATHER ? gather_row(m0 + r) : (m0 + r);
        const float* src = (const float*)Ain + (size_t)arow * 192 + half * 96;
        __nv_bfloat16* dstp = As + r * SROW + half * 96;
        float s = 0.f, q = 0.f;
#pragma unroll
        for (int c = 0; c < 24; c++) {
            float4 v = *(const float4*)(src + c * 4);
            s += v.x + v.y + v.z + v.w;
            q += v.x * v.x + v.y * v.y + v.z * v.z + v.w * v.w;
            __nv_bfloat162 p0, p1;
            p0.x = __float2bfloat16(v.x); p0.y = __float2bfloat16(v.y);
            p1.x = __float2bfloat16(v.z); p1.y = __float2bfloat16(v.w);
            *(__nv_bfloat162*)(dstp + c * 4)     = p0;
            *(__nv_bfloat162*)(dstp + c * 4 + 2) = p1;
        }
        s += __shfl_xor_sync(0xffffffffu, s, 1);
        q += __shfl_xor_sync(0xffffffffu, q, 1);
        float mu  = s * (1.f / 192.f);
        float var = q * (1.f / 192.f) - mu * mu;
        if (half == 0) { sMu[r] = mu; sInv[r] = rsqrtf(var + 1e-5f); }
        asm volatile("cp.async.commit_group;\n");
    } else {
        const int r = t >> 1, col = (t & 1) * 96;
        const int arow = GATHER ? gather_row(m0 + r) : (m0 + r);
        const __nv_bfloat16* src = (const __nv_bfloat16*)Ain + (size_t)arow * 192 + col;
        unsigned dst = smem_u32(As + r * SROW + col);
#pragma unroll
        for (int c = 0; c < 12; c++)
            asm volatile("cp.async.cg.shared.global [%0], [%1], 16;\n"
                :: "r"(dst + c * 16), "l"(src + c * 8));
        asm volatile("cp.async.commit_group;\n");
    }
    asm volatile("cp.async.wait_group 0;\n");
    __syncthreads();

    // ---- compute: 12 k-steps of 16, no barriers
    float acc[4][4][4];
#pragma unroll
    for (int i = 0; i < 4; i++)
#pragma unroll
        for (int j = 0; j < 4; j++)
#pragma unroll
            for (int q = 0; q < 4; q++) acc[i][j][q] = 0.f;

    const int r16 = lane & 15, chh = lane >> 4;
#pragma unroll
    for (int kk = 0; kk < 12; kk++) {
        unsigned a[4][4], b[2][4];
#pragma unroll
        for (int i = 0; i < 4; i++) {
            unsigned addr = smem_u32(As + (wm * 64 + i * 16 + r16) * SROW + kk * 16 + chh * 8);
            asm volatile("ldmatrix.sync.aligned.m8n8.x4.shared.b16 {%0,%1,%2,%3}, [%4];"
                : "=r"(a[i][0]), "=r"(a[i][1]), "=r"(a[i][2]), "=r"(a[i][3]) : "r"(addr));
        }
#pragma unroll
        for (int j2 = 0; j2 < 2; j2++) {
            unsigned addr = smem_u32(Bs + (wn * 32 + j2 * 16 + r16) * SROW + kk * 16 + chh * 8);
            asm volatile("ldmatrix.sync.aligned.m8n8.x4.shared.b16 {%0,%1,%2,%3}, [%4];"
                : "=r"(b[j2][0]), "=r"(b[j2][1]), "=r"(b[j2][2]), "=r"(b[j2][3]) : "r"(addr));
        }
#pragma unroll
        for (int i = 0; i < 4; i++)
#pragma unroll
            for (int j = 0; j < 4; j++) {
                unsigned b0 = b[j >> 1][j & 1], b1 = b[j >> 1][(j & 1) + 2];
                asm volatile(
                    "mma.sync.aligned.m16n8k16.row.col.f32.bf16.bf16.f32 "
                    "{%0,%1,%2,%3}, {%4,%5,%6,%7}, {%8,%9}, {%0,%1,%2,%3};"
                    : "+f"(acc[i][j][0]), "+f"(acc[i][j][1]), "+f"(acc[i][j][2]), "+f"(acc[i][j][3])
                    : "r"(a[i][0]), "r"(a[i][1]), "r"(a[i][2]), "r"(a[i][3]), "r"(b0), "r"(b1));
            }
    }

    // ---- epilogue
#pragma unroll
    for (int i = 0; i < 4; i++) {
        int lr0 = wm * 64 + i * 16 + (lane >> 2);
#pragma unroll
        for (int j = 0; j < 4; j++) {
            int c = n0 + wn * 32 + j * 8 + (lane & 3) * 2;
            if (c < N) {
#pragma unroll
                for (int h = 0; h < 2; h++) {
                    int lr = lr0 + h * 8;
                    int r  = m0 + lr;
                    float v0 = acc[i][j][h * 2 + 0];
                    float v1 = acc[i][j][h * 2 + 1];
                    if (LNF) {
                        float mu = sMu[lr], inv = sInv[lr];
                        v0 = inv * (v0 - mu * Svec[c])     + Tvec[c];
                        v1 = inv * (v1 - mu * Svec[c + 1]) + Tvec[c + 1];
                    } else if (bias) {
                        v0 += __ldg(&bias[c]); v1 += __ldg(&bias[c + 1]);
                    }
                    if (EPI == 1) {
                        v0 = 0.5f * v0 * (1.f + erff(v0 * 0.70710678118654752f));
                        v1 = 0.5f * v1 * (1.f + erff(v1 * 0.70710678118654752f));
                    }
                    if (EPI == 2) {
                        int orow = gather_row(r);
                        size_t off = (size_t)orow * N + c;
                        float2 rv = *(const float2*)(res + off);
                        float2 ov; ov.x = v0 + rv.x; ov.y = v1 + rv.y;
                        *(float2*)((float*)Cout + off) = ov;
                    } else {
                        __nv_bfloat162 p;
                        p.x = __float2bfloat16(v0); p.y = __float2bfloat16(v1);
                        *(__nv_bfloat162*)((__nv_bfloat16*)Cout + (size_t)r * N + c) = p;
                    }
                }
            }
        }
    }
}

// ---------------- pipelined GEMM for K=768 (MLP2): +bias +res fp32 out ----------------
#define KSTEP 32
#define SPAD 40

__global__ void __launch_bounds__(256) gemm_mma2(
    const __nv_bfloat16* __restrict__ A, const __nv_bfloat16* __restrict__ W,
    const float* __restrict__ bias, const float* __restrict__ res,
    float* __restrict__ Cout, int K, int N)
{
    __shared__ __nv_bfloat16 As[3][128][SPAD];
    __shared__ __nv_bfloat16 Bs[3][128][SPAD];
    const int m0 = blockIdx.x * 128, n0 = blockIdx.y * 128;
    const int t = threadIdx.x, lane = t & 31, wid = t >> 5;
    const int wm = wid & 1, wn = wid >> 1;

    const int lr = t >> 2;
    const int lch = (t & 3) * 8;
    const __nv_bfloat16* Ap0 = A + (size_t)(m0 + lr) * K + lch;
    const __nv_bfloat16* Ap1 = A + (size_t)(m0 + 64 + lr) * K + lch;
    int bg0 = n0 + lr;      if (bg0 >= N) bg0 = 0;
    int bg1 = n0 + 64 + lr; if (bg1 >= N) bg1 = 0;
    const __nv_bfloat16* Wp0 = W + (size_t)bg0 * K + lch;
    const __nv_bfloat16* Wp1 = W + (size_t)bg1 * K + lch;

    float acc[4][4][4];
#pragma unroll
    for (int i = 0; i < 4; i++)
#pragma unroll
        for (int j = 0; j < 4; j++)
#pragma unroll
            for (int q = 0; q < 4; q++) acc[i][j][q] = 0.f;

    const int nk = K / KSTEP;

#define LOAD_STAGE(st, ks)                                                              \
    do {                                                                                \
        unsigned _a0 = smem_u32(&As[st][lr][lch]);                                      \
        unsigned _a1 = smem_u32(&As[st][64 + lr][lch]);                                 \
        unsigned _b0 = smem_u32(&Bs[st][lr][lch]);                                      \
        unsigned _b1 = smem_u32(&Bs[st][64 + lr][lch]);                                 \
        asm volatile("cp.async.cg.shared.global [%0], [%1], 16;\n" :: "r"(_a0), "l"(Ap0 + (ks) * KSTEP)); \
        asm volatile("cp.async.cg.shared.global [%0], [%1], 16;\n" :: "r"(_a1), "l"(Ap1 + (ks) * KSTEP)); \
        asm volatile("cp.async.cg.shared.global [%0], [%1], 16;\n" :: "r"(_b0), "l"(Wp0 + (ks) * KSTEP)); \
        asm volatile("cp.async.cg.shared.global [%0], [%1], 16;\n" :: "r"(_b1), "l"(Wp1 + (ks) * KSTEP)); \
        asm volatile("cp.async.commit_group;\n");                                       \
    } while (0)

    LOAD_STAGE(0, 0);
    LOAD_STAGE(1, 1);

    const int r16 = lane & 15, chh = lane >> 4;

    for (int ks = 0; ks < nk; ks++) {
        if (ks + 1 < nk) asm volatile("cp.async.wait_group 1;\n");
        else             asm volatile("cp.async.wait_group 0;\n");
        __syncthreads();

        if (ks + 2 < nk) {
            int st = (ks + 2) % 3;
            LOAD_STAGE(st, ks + 2);
        }

        const int buf = ks % 3;
#pragma unroll
        for (int kk = 0; kk < 2; kk++) {
            unsigned a[4][4], b[2][4];
#pragma unroll
            for (int i = 0; i < 4; i++) {
                unsigned addr = smem_u32(&As[buf][wm * 64 + i * 16 + r16][kk * 16 + chh * 8]);
                asm volatile("ldmatrix.sync.aligned.m8n8.x4.shared.b16 {%0,%1,%2,%3}, [%4];"
                    : "=r"(a[i][0]), "=r"(a[i][1]), "=r"(a[i][2]), "=r"(a[i][3]) : "r"(addr));
            }
#pragma unroll
            for (int j2 = 0; j2 < 2; j2++) {
                unsigned addr = smem_u32(&Bs[buf][wn * 32 + j2 * 16 + r16][kk * 16 + chh * 8]);
                asm volatile("ldmatrix.sync.aligned.m8n8.x4.shared.b16 {%0,%1,%2,%3}, [%4];"
                    : "=r"(b[j2][0]), "=r"(b[j2][1]), "=r"(b[j2][2]), "=r"(b[j2][3]) : "r"(addr));
            }
#pragma unroll
            for (int i = 0; i < 4; i++)
#pragma unroll
                for (int j = 0; j < 4; j++) {
                    unsigned b0 = b[j >> 1][j & 1], b1 = b[j >> 1][(j & 1) + 2];
                    asm volatile(
                        "mma.sync.aligned.m16n8k16.row.col.f32.bf16.bf16.f32 "
                        "{%0,%1,%2,%3}, {%4,%5,%6,%7}, {%8,%9}, {%0,%1,%2,%3};"
                        : "+f"(acc[i][j][0]), "+f"(acc[i][j][1]), "+f"(acc[i][j][2]), "+f"(acc[i][j][3])
                        : "r"(a[i][0]), "r"(a[i][1]), "r"(a[i][2]), "r"(a[i][3]), "r"(b0), "r"(b1));
                }
        }
    }
#undef LOAD_STAGE

#pragma unroll
    for (int i = 0; i < 4; i++) {
        int rbase = m0 + wm * 64 + i * 16 + (lane >> 2);
#pragma unroll
        for (int j = 0; j < 4; j++) {
            int c = n0 + wn * 32 + j * 8 + (lane & 3) * 2;
            if (c < N) {
#pragma unroll
                for (int h = 0; h < 2; h++) {
                    int r = rbase + h * 8;
                    float v0 = acc[i][j][h * 2 + 0] + __ldg(&bias[c]);
                    float v1 = acc[i][j][h * 2 + 1] + __ldg(&bias[c + 1]);
                    size_t off = (size_t)r * N + c;
                    float2 rv = *(const float2*)(res + off);
                    float2 ov; ov.x = v0 + rv.x; ov.y = v1 + rv.y;
                    *(float2*)(Cout + off) = ov;
                }
            }
        }
    }
}

// ---------------- windowed attention (unchanged) ----------------
__device__ __forceinline__ int region(int p) { return p < 248 ? 0 : (p < 252 ? 1 : 2); }

__global__ void __launch_bounds__(64) attn_kernel(const __nv_bfloat16* __restrict__ qkv,
                                                  const float* __restrict__ rpb,
                                                  __nv_bfloat16* __restrict__ out) {
    __shared__ float sk[64][32];
    __shared__ float sv[64][32];
    __shared__ float sp[64][65];
    __shared__ float srpb[225];

    const int win = blockIdx.x;
    const int h   = blockIdx.y;
    const int n   = threadIdx.x;

    for (int i = n; i < 225; i += 64) srpb[i] = rpb[i * HEADS + h];

    const size_t base = (size_t)(win * 64 + n) * (3 * CH) + h * HD;
    const float scale = 0.17677669529663687f;

    float q[32];
    {
        const __nv_bfloat162* qp = (const __nv_bfloat162*)(qkv + base);
        const __nv_bfloat162* kp = (const __nv_bfloat162*)(qkv + base + CH);
        const __nv_bfloat162* vp = (const __nv_bfloat162*)(qkv + base + 2 * CH);
#pragma unroll
        for (int i = 0; i < 16; i++) {
            float2 fq = __bfloat1622float2(qp[i]);
            float2 fk = __bfloat1622float2(kp[i]);
            float2 fv = __bfloat1622float2(vp[i]);
            q[2 * i] = fq.x * scale; q[2 * i + 1] = fq.y * scale;
            sk[n][2 * i] = fk.x; sk[n][2 * i + 1] = fk.y;
            sv[n][2 * i] = fv.x; sv[n][2 * i + 1] = fv.y;
        }
    }
    __syncthreads();

    const int rem = win & 1023;
    const int wh = rem >> 5, ww = rem & 31;
    const int ri = n >> 3, ci = n & 7;
    const int idi = region(wh * 8 + ri) * 3 + region(ww * 8 + ci);

    float mx = -1e30f;
    for (int j = 0; j < 64; j++) {
        float a = 0.f;
#pragma unroll
        for (int d4 = 0; d4 < 8; d4++) {
            float4 kv = *(const float4*)&sk[j][d4 * 4];
            a = fmaf(q[d4 * 4 + 0], kv.x, a);
            a = fmaf(q[d4 * 4 + 1], kv.y, a);
            a = fmaf(q[d4 * 4 + 2], kv.z, a);
            a = fmaf(q[d4 * 4 + 3], kv.w, a);
        }
        int rj = j >> 3, cj = j & 7;
        a += srpb[(ri - rj + 7) * 15 + (ci - cj + 7)];
        int idj = region(wh * 8 + rj) * 3 + region(ww * 8 + cj);
        if (idi != idj) a -= 100.f;
        sp[n][j] = a;
        mx = fmaxf(mx, a);
    }

    float sum = 0.f;
    for (int j = 0; j < 64; j++) {
        float e = __expf(sp[n][j] - mx);
        sp[n][j] = e;
        sum += e;
    }
    float inv = 1.f / sum;

    float o[32];
#pragma unroll
    for (int d = 0; d < 32; d++) o[d] = 0.f;
    for (int j = 0; j < 64; j++) {
        float p = sp[n][j];
#pragma unroll
        for (int d4 = 0; d4 < 8; d4++) {
            float4 vv = *(const float4*)&sv[j][d4 * 4];
            o[d4 * 4 + 0] = fmaf(p, vv.x, o[d4 * 4 + 0]);
            o[d4 * 4 + 1] = fmaf(p, vv.y, o[d4 * 4 + 1]);
            o[d4 * 4 + 2] = fmaf(p, vv.z, o[d4 * 4 + 2]);
            o[d4 * 4 + 3] = fmaf(p, vv.w, o[d4 * 4 + 3]);
        }
    }

    __nv_bfloat16* op = out + (size_t)(win * 64 + n) * CH + h * HD;
#pragma unroll
    for (int d2 = 0; d2 < 16; d2++) {
        __nv_bfloat162 p;
        p.x = __float2bfloat16(o[2 * d2] * inv);
        p.y = __float2bfloat16(o[2 * d2 + 1] * inv);
        *(__nv_bfloat162*)&op[2 * d2] = p;
    }
}

// ---------------- launcher ----------------
extern "C" void kernel_launch(void* const* d_in, const int* in_sizes, int n_in,
                              void* d_out, int out_size) {
    const float* x       = (const float*)d_in[0];
    const float* norm1_g = (const float*)d_in[1];
    const float* norm1_b = (const float*)d_in[2];
    const float* qkv_w   = (const float*)d_in[3];
    const float* rpb     = (const float*)d_in[4];
    const float* proj_w  = (const float*)d_in[5];
    const float* proj_b  = (const float*)d_in[6];
    const float* norm2_g = (const float*)d_in[7];
    const float* norm2_b = (const float*)d_in[8];
    const float* mlp_w1  = (const float*)d_in[9];
    const float* mlp_b1  = (const float*)d_in[10];
    const float* mlp_w2  = (const float*)d_in[11];
    const float* mlp_b2  = (const float*)d_in[12];
    float* out = (float*)d_out;

    __nv_bfloat16 *qkvb, *attnb, *hid, *wbuf;
    float *x1, *Sq, *Tq, *S1, *T1;
    cudaGetSymbolAddress((void**)&qkvb,  gb_qkv);
    cudaGetSymbolAddress((void**)&attnb, gb_attn);
    cudaGetSymbolAddress((void**)&x1,    g_x1);
    cudaGetSymbolAddress((void**)&hid,   gb_hid);
    cudaGetSymbolAddress((void**)&wbuf,  gb_w);
    cudaGetSymbolAddress((void**)&Sq,    g_Sq);
    cudaGetSymbolAddress((void**)&Tq,    g_Tq);
    cudaGetSymbolAddress((void**)&S1,    g_S1);
    cudaGetSymbolAddress((void**)&T1,    g_T1);

    __nv_bfloat16* wq = wbuf;
    __nv_bfloat16* wp = wbuf + 576 * 192;
    __nv_bfloat16* w1 = wp   + 192 * 192;
    __nv_bfloat16* w2 = w1   + 768 * 192;

    const size_t SMEMSZ = (size_t)2 * 128 * SROW * 2 + 256 * 4;  // A+B tiles + stats
    cudaFuncSetAttribute(gemm_fullk<0, true,  true >, cudaFuncAttributeMaxDynamicSharedMemorySize, (int)SMEMSZ);
    cudaFuncSetAttribute(gemm_fullk<2, false, false>, cudaFuncAttributeMaxDynamicSharedMemorySize, (int)SMEMSZ);
    cudaFuncSetAttribute(gemm_fullk<1, false, true >, cudaFuncAttributeMaxDynamicSharedMemorySize, (int)SMEMSZ);

    const int M = MTOT;

    // weight prep: LN-folded (qkv, mlp1) + plain (proj, mlp2)
    wprep_kernel<<<576, 32>>>(qkv_w,  norm1_g, norm1_b, nullptr, wq, Sq, Tq);
    wprep_kernel<<<768, 32>>>(mlp_w1, norm2_g, norm2_b, mlp_b1,  w1, S1, T1);
    f2bf_kernel<<<(192 * 192 + 255) / 256, 256>>>(proj_w, wp, 192 * 192);
    f2bf_kernel<<<(192 * 768 + 255) / 256, 256>>>(mlp_w2, w2, 192 * 768);

    // QKV = LN1-fold GEMM on raw x, gathered rows (shift + window partition)
    gemm_fullk<0, true, true><<<dim3(M / 128, 5), 256, SMEMSZ>>>(
        x, wq, Sq, Tq, nullptr, nullptr, qkvb, 3 * CH);

    // attention
    attn_kernel<<<dim3(2048, HEADS), 64>>>(qkvb, rpb, attnb);

    // proj + scatter + residual -> x1 (fp32)
    gemm_fullk<2, false, false><<<dim3(M / 128, 2), 256, SMEMSZ>>>(
        attnb, wp, nullptr, nullptr, proj_b, x, x1, CH);

    // MLP1 = LN2-fold GEMM on raw x1, + GELU -> bf16
    gemm_fullk<1, false, true><<<dim3(M / 128, 6), 256, SMEMSZ>>>(
        x1, w1, S1, T1, nullptr, nullptr, hid, HIDDEN);

    // MLP2 (pipelined, K=768) + bias + residual -> fp32 out
    gemm_mma2<<<dim3(M / 128, 2), 256>>>(hid, w2, mlp_b2, x1, out, HIDDEN, CH);
}